// round 8
// baseline (speedup 1.0000x reference)
#include <cuda_runtime.h>
#include <cuda_bf16.h>
#include <cuda_fp16.h>
#include <cstdint>

#define N_NODES 50000
#define N_EDGES 800000
#define CAP 64

// ---------------- scratch (device globals; no allocation allowed) ----------
__device__ int    g_count[N_NODES];           // zero-init; re-zeroed by agg64
__device__ int    g_slot[N_NODES * CAP];
__device__ __half g_zh[N_NODES * 128];        // GEMM output, fp16
__device__ float  g_h[N_NODES * 128];         // agg output, fp32
// packed split weights: per (n, k-pair): {hi[k],hi[k+1]} , {lo[k],lo[k+1]}
// W1: 8192 uint2 | W2: 8192 | W3: 4096
__device__ uint2  g_wp[20480];

// ---------------- small helpers ----------------
__device__ __forceinline__ uint32_t smem_u32(const void* p) {
    uint32_t a;
    asm("{ .reg .u64 t; cvta.to.shared.u64 t, %1; cvt.u32.u64 %0, t; }"
        : "=r"(a) : "l"(p));
    return a;
}

#define LDMATRIX_X4(r, addr) \
    asm volatile("ldmatrix.sync.aligned.m8n8.x4.shared.b16 {%0,%1,%2,%3}, [%4];" \
                 : "=r"((r)[0]), "=r"((r)[1]), "=r"((r)[2]), "=r"((r)[3]) \
                 : "r"(addr))

#define MMA_BF16(acc, a, b0, b1) \
    asm volatile("mma.sync.aligned.m16n8k16.row.col.f32.bf16.bf16.f32 " \
                 "{%0,%1,%2,%3}, {%4,%5,%6,%7}, {%8,%9}, {%0,%1,%2,%3};" \
                 : "+f"((acc)[0]), "+f"((acc)[1]), "+f"((acc)[2]), "+f"((acc)[3]) \
                 : "r"((a)[0]), "r"((a)[1]), "r"((a)[2]), "r"((a)[3]), \
                   "r"(b0), "r"(b1))

__device__ __forceinline__ uint32_t pack_bf162(float a, float b) {
    __nv_bfloat162 p;
    p.x = __float2bfloat16_rn(a);
    p.y = __float2bfloat16_rn(b);
    return *reinterpret_cast<uint32_t*>(&p);
}

// accumulate 8 fp16 values (as uint4) into 8 fp32 accumulators (exact path)
__device__ __forceinline__ void add8h(float* acc, uint4 v) {
    const __half2* h = reinterpret_cast<const __half2*>(&v);
    #pragma unroll
    for (int i = 0; i < 4; i++) {
        float2 f = __half22float2(h[i]);
        acc[2 * i]     += f.x;
        acc[2 * i + 1] += f.y;
    }
}

// sum a quad of fp16 rows in packed fp16 (3 roundings), flush to fp32
__device__ __forceinline__ void quad_flush(float* acc, uint4 v0, uint4 v1,
                                           uint4 v2, uint4 v3) {
    const __half2* p0 = reinterpret_cast<const __half2*>(&v0);
    const __half2* p1 = reinterpret_cast<const __half2*>(&v1);
    const __half2* p2 = reinterpret_cast<const __half2*>(&v2);
    const __half2* p3 = reinterpret_cast<const __half2*>(&v3);
    #pragma unroll
    for (int i = 0; i < 4; i++) {
        __half2 s = __hadd2(__hadd2(p0[i], p1[i]), __hadd2(p2[i], p3[i]));
        float2 f = __half22float2(s);
        acc[2 * i]     += f.x;
        acc[2 * i + 1] += f.y;
    }
}

// ---------------- setup: build packed split-W (counts zeroed by agg64) -----
__global__ void setup_kernel(const float* __restrict__ W1,
                             const float* __restrict__ W2,
                             const float* __restrict__ W3) {
    int i = blockIdx.x * blockDim.x + threadIdx.x;
    if (i >= 20480) return;
    const float* W;
    int rel;
    if (i < 8192)       { W = W1; rel = i; }
    else if (i < 16384) { W = W2; rel = i - 8192; }
    else                { W = W3; rel = i - 16384; }
    int n  = rel >> 6;
    int kp = rel & 63;
    float v0 = W[n * 128 + kp * 2 + 0];
    float v1 = W[n * 128 + kp * 2 + 1];
    __nv_bfloat16 h0 = __float2bfloat16_rn(v0);
    __nv_bfloat16 h1 = __float2bfloat16_rn(v1);
    float l0 = v0 - __bfloat162float(h0);
    float l1 = v1 - __bfloat162float(h1);
    __nv_bfloat162 hi; hi.x = h0; hi.y = h1;
    uint2 out;
    out.x = *reinterpret_cast<uint32_t*>(&hi);
    out.y = pack_bf162(l0, l1);
    g_wp[i] = out;
}

// ---------------- bucket adjacency build ----------------
__global__ void fill_kernel(const int* __restrict__ src,
                            const int* __restrict__ dst) {
    int e = blockIdx.x * blockDim.x + threadIdx.x;
    if (e < N_EDGES) {
        int d = dst[e];
        int p = atomicAdd(&g_count[d], 1);
        if (p < CAP) g_slot[d * CAP + p] = src[e];
    }
}

// ---------------- mma.sync split-bf16 GEMM: Zh[128-tile][N] = A @ W^T ------
template <int N>
__global__ void __launch_bounds__(128, 2) mma_gemm(
    const float* __restrict__ A, const uint2* __restrict__ Wp,
    __half* __restrict__ Zh) {
    constexpr int NT  = N / 8;
    constexpr int LDA = 136;

    extern __shared__ __nv_bfloat16 smem[];
    __nv_bfloat16* Ash = smem;
    __nv_bfloat16* Asl = smem + 128 * LDA;

    const int tid  = threadIdx.x;
    const int wid  = tid >> 5;
    const int lane = tid & 31;
    const int m0   = blockIdx.x * 128;

    for (int t = tid; t < 4096; t += 128) {
        int r = t >> 5;
        int c = (t & 31) << 2;
        int m = m0 + r;
        float4 v = make_float4(0.f, 0.f, 0.f, 0.f);
        if (m < N_NODES)
            v = *reinterpret_cast<const float4*>(A + (size_t)m * 128 + c);
        __nv_bfloat16 h0 = __float2bfloat16_rn(v.x);
        __nv_bfloat16 h1 = __float2bfloat16_rn(v.y);
        __nv_bfloat16 h2 = __float2bfloat16_rn(v.z);
        __nv_bfloat16 h3 = __float2bfloat16_rn(v.w);
        __nv_bfloat162 hp0; hp0.x = h0; hp0.y = h1;
        __nv_bfloat162 hp1; hp1.x = h2; hp1.y = h3;
        uint2 hv, lv;
        hv.x = *reinterpret_cast<uint32_t*>(&hp0);
        hv.y = *reinterpret_cast<uint32_t*>(&hp1);
        lv.x = pack_bf162(v.x - __bfloat162float(h0), v.y - __bfloat162float(h1));
        lv.y = pack_bf162(v.z - __bfloat162float(h2), v.w - __bfloat162float(h3));
        *reinterpret_cast<uint2*>(Ash + r * LDA + c) = hv;
        *reinterpret_cast<uint2*>(Asl + r * LDA + c) = lv;
    }
    __syncthreads();

    float acc[2][NT][4];
    #pragma unroll
    for (int mt = 0; mt < 2; mt++)
        #pragma unroll
        for (int nt = 0; nt < NT; nt++)
            #pragma unroll
            for (int i = 0; i < 4; i++) acc[mt][nt][i] = 0.0f;

    const int wrow = wid * 32;
    const int lrow = lane & 15;
    const int kgrp = (lane >> 4) * 8;
    const int wn   = lane >> 2;
    const int wkp  = lane & 3;

    #pragma unroll
    for (int ks = 0; ks < 8; ks++) {
        const int k0 = ks * 16;
        uint32_t ah[2][4], al[2][4];
        #pragma unroll
        for (int mt = 0; mt < 2; mt++) {
            uint32_t ad = smem_u32(Ash + (wrow + mt * 16 + lrow) * LDA + k0 + kgrp);
            LDMATRIX_X4(ah[mt], ad);
            uint32_t bd = smem_u32(Asl + (wrow + mt * 16 + lrow) * LDA + k0 + kgrp);
            LDMATRIX_X4(al[mt], bd);
        }
        #pragma unroll
        for (int nt = 0; nt < NT; nt++) {
            const uint2* wp = Wp + (size_t)(nt * 8 + wn) * 64 + (k0 >> 1) + wkp;
            uint2 p0 = wp[0];
            uint2 p1 = wp[4];
            #pragma unroll
            for (int mt = 0; mt < 2; mt++) {
                MMA_BF16(acc[mt][nt], ah[mt], p0.x, p1.x);
                MMA_BF16(acc[mt][nt], ah[mt], p0.y, p1.y);
                MMA_BF16(acc[mt][nt], al[mt], p0.x, p1.x);
            }
        }
    }

    #pragma unroll
    for (int mt = 0; mt < 2; mt++) {
        int r0 = m0 + wrow + mt * 16 + (lane >> 2);
        #pragma unroll
        for (int nt = 0; nt < NT; nt++) {
            int col = nt * 8 + (lane & 3) * 2;
            if (r0 < N_NODES) {
                __half2 hv = __floats2half2_rn(acc[mt][nt][0], acc[mt][nt][1]);
                *reinterpret_cast<__half2*>(Zh + (size_t)r0 * N + col) = hv;
            }
            if (r0 + 8 < N_NODES) {
                __half2 hv = __floats2half2_rn(acc[mt][nt][2], acc[mt][nt][3]);
                *reinterpret_cast<__half2*>(Zh + (size_t)(r0 + 8) * N + col) = hv;
            }
        }
    }
}

// ---------------- gather + self + inv-scale + relu (fp16 z, HADD2 quads) ---
// Warp = 2 groups of 16 lanes; group g handles neighbors g, g+2, g+4, ...
// Fast path: 4 neighbors per group summed in packed fp16 (3 roundings per
// partial), flushed to fp32. Tail (<4) accumulated exactly in fp32.
__global__ void agg128_kernel(const __half* __restrict__ Z,
                              float* __restrict__ H) {
    int node = (blockIdx.x * blockDim.x + threadIdx.x) >> 5;
    if (node >= N_NODES) return;
    int lane = threadIdx.x & 31;
    int g = lane >> 4;
    int c = lane & 15;

    float acc[8];
    #pragma unroll
    for (int i = 0; i < 8; i++) acc[i] = 0.f;

    if (g == 0) {
        uint4 v = *reinterpret_cast<const uint4*>(Z + (size_t)node * 128 + c * 8);
        add8h(acc, v);
    }

    int cnt = g_count[node];
    int deg = cnt < CAP ? cnt : CAP;
    const int* sl = &g_slot[node * CAP];

    int j = g;
    for (; j + 6 < deg; j += 8) {
        int i0 = sl[j], i1 = sl[j + 2], i2 = sl[j + 4], i3 = sl[j + 6];
        uint4 v0 = *reinterpret_cast<const uint4*>(Z + (size_t)i0 * 128 + c * 8);
        uint4 v1 = *reinterpret_cast<const uint4*>(Z + (size_t)i1 * 128 + c * 8);
        uint4 v2 = *reinterpret_cast<const uint4*>(Z + (size_t)i2 * 128 + c * 8);
        uint4 v3 = *reinterpret_cast<const uint4*>(Z + (size_t)i3 * 128 + c * 8);
        quad_flush(acc, v0, v1, v2, v3);
    }
    for (; j < deg; j += 2) {
        int s = sl[j];
        uint4 v = *reinterpret_cast<const uint4*>(Z + (size_t)s * 128 + c * 8);
        add8h(acc, v);
    }

    __syncwarp();
    #pragma unroll
    for (int i = 0; i < 8; i++)
        acc[i] += __shfl_down_sync(0xffffffffu, acc[i], 16);

    if (g == 0) {
        float sc = 1.0f / ((float)cnt + 1.0f);
        float4 o0 = make_float4(fmaxf(acc[0] * sc, 0.f), fmaxf(acc[1] * sc, 0.f),
                                fmaxf(acc[2] * sc, 0.f), fmaxf(acc[3] * sc, 0.f));
        float4 o1 = make_float4(fmaxf(acc[4] * sc, 0.f), fmaxf(acc[5] * sc, 0.f),
                                fmaxf(acc[6] * sc, 0.f), fmaxf(acc[7] * sc, 0.f));
        float4* dst = reinterpret_cast<float4*>(H + (size_t)node * 128 + c * 8);
        dst[0] = o0;
        dst[1] = o1;
    }
}

// Final layer: 64-dim fp16 z. Warp = 4 groups of 8 lanes; group g handles
// neighbors g, g+4, ... Also re-zeroes g_count for graph-replay determinism.
__global__ void agg64_kernel(const __half* __restrict__ Z,
                             float* __restrict__ out) {
    int node = (blockIdx.x * blockDim.x + threadIdx.x) >> 5;
    if (node >= N_NODES) return;
    int lane = threadIdx.x & 31;
    int g = lane >> 3;
    int c = lane & 7;

    float acc[8];
    #pragma unroll
    for (int i = 0; i < 8; i++) acc[i] = 0.f;

    if (g == 0) {
        uint4 v = *reinterpret_cast<const uint4*>(Z + (size_t)node * 64 + c * 8);
        add8h(acc, v);
    }

    int cnt = g_count[node];
    int deg = cnt < CAP ? cnt : CAP;
    const int* sl = &g_slot[node * CAP];

    int j = g;
    for (; j + 12 < deg; j += 16) {
        int i0 = sl[j], i1 = sl[j + 4], i2 = sl[j + 8], i3 = sl[j + 12];
        uint4 v0 = *reinterpret_cast<const uint4*>(Z + (size_t)i0 * 64 + c * 8);
        uint4 v1 = *reinterpret_cast<const uint4*>(Z + (size_t)i1 * 64 + c * 8);
        uint4 v2 = *reinterpret_cast<const uint4*>(Z + (size_t)i2 * 64 + c * 8);
        uint4 v3 = *reinterpret_cast<const uint4*>(Z + (size_t)i3 * 64 + c * 8);
        quad_flush(acc, v0, v1, v2, v3);
    }
    for (; j < deg; j += 4) {
        int s = sl[j];
        uint4 v = *reinterpret_cast<const uint4*>(Z + (size_t)s * 64 + c * 8);
        add8h(acc, v);
    }

    __syncwarp();
    #pragma unroll
    for (int i = 0; i < 8; i++)
        acc[i] += __shfl_down_sync(0xffffffffu, acc[i], 16);
    #pragma unroll
    for (int i = 0; i < 8; i++)
        acc[i] += __shfl_down_sync(0xffffffffu, acc[i], 8);

    if (lane < 8) {
        float sc = 1.0f / ((float)cnt + 1.0f);
        float4 o0 = make_float4(fmaxf(acc[0] * sc, 0.f), fmaxf(acc[1] * sc, 0.f),
                                fmaxf(acc[2] * sc, 0.f), fmaxf(acc[3] * sc, 0.f));
        float4 o1 = make_float4(fmaxf(acc[4] * sc, 0.f), fmaxf(acc[5] * sc, 0.f),
                                fmaxf(acc[6] * sc, 0.f), fmaxf(acc[7] * sc, 0.f));
        float4* dst = reinterpret_cast<float4*>(out + (size_t)node * 64 + c * 8);
        dst[0] = o0;
        dst[1] = o1;
    }
    if (lane == 0) g_count[node] = 0;   // reset for next launch / replay
}

// ---------------- launch ----------------
extern "C" void kernel_launch(void* const* d_in, const int* in_sizes, int n_in,
                              void* d_out, int out_size) {
    const float* x   = (const float*)d_in[0];
    const int*   ei  = (const int*)d_in[1];
    const float* W1  = (const float*)d_in[2];
    const float* W2  = (const float*)d_in[3];
    const float* W3  = (const float*)d_in[4];
    float*       out = (float*)d_out;

    const int* src = ei;
    const int* dst = ei + N_EDGES;

    __half* zh = nullptr;
    float*  h  = nullptr;
    uint2*  wp = nullptr;
    cudaGetSymbolAddress((void**)&zh, g_zh);
    cudaGetSymbolAddress((void**)&h,  g_h);
    cudaGetSymbolAddress((void**)&wp, g_wp);

    constexpr int SMEM_A = 2 * 128 * 136 * 2;   // 69632 bytes
    cudaFuncSetAttribute(mma_gemm<128>, cudaFuncAttributeMaxDynamicSharedMemorySize, SMEM_A);
    cudaFuncSetAttribute(mma_gemm<64>,  cudaFuncAttributeMaxDynamicSharedMemorySize, SMEM_A);

    const int TPB = 256;
    const int gemm_blocks = (N_NODES + 127) / 128;           // 391
    const int agg_blocks  = (N_NODES * 32 + TPB - 1) / TPB;  // 6250

    setup_kernel<<<80, TPB>>>(W1, W2, W3);
    fill_kernel<<<(N_EDGES + TPB - 1) / TPB, TPB>>>(src, dst);

    // layer 1
    mma_gemm<128><<<gemm_blocks, 128, SMEM_A>>>(x, wp, zh);
    agg128_kernel<<<agg_blocks, TPB>>>(zh, h);
    // layer 2
    mma_gemm<128><<<gemm_blocks, 128, SMEM_A>>>(h, wp + 8192, zh);
    agg128_kernel<<<agg_blocks, TPB>>>(zh, h);
    // layer 3 (N=64), final relu + write out
    mma_gemm<64><<<gemm_blocks, 128, SMEM_A>>>(h, wp + 16384, zh);
    agg64_kernel<<<agg_blocks, TPB>>>(zh, out);
}

// round 9
// speedup vs baseline: 1.1258x; 1.1258x over previous
#include <cuda_runtime.h>
#include <cuda_bf16.h>
#include <cuda_fp16.h>
#include <cstdint>

#define N_NODES 50000
#define N_EDGES 800000
#define CAP 64
#define LDA 136

// ---------------- scratch (device globals; no allocation allowed) ----------
__device__ int    g_count[N_NODES];           // zero-init; re-zeroed by agg64
__device__ int    g_slot[N_NODES * CAP];
__device__ __half g_za[N_NODES * 128];        // z ping
__device__ __half g_zb[N_NODES * 128];        // z pong
// packed split weights: per (n, k-pair): {hi[k],hi[k+1]} , {lo[k],lo[k+1]}
// W1: 8192 uint2 | W2: 8192 | W3: 4096
__device__ uint2  g_wp[20480];

// ---------------- small helpers ----------------
__device__ __forceinline__ uint32_t smem_u32(const void* p) {
    uint32_t a;
    asm("{ .reg .u64 t; cvta.to.shared.u64 t, %1; cvt.u32.u64 %0, t; }"
        : "=r"(a) : "l"(p));
    return a;
}

#define LDMATRIX_X4(r, addr) \
    asm volatile("ldmatrix.sync.aligned.m8n8.x4.shared.b16 {%0,%1,%2,%3}, [%4];" \
                 : "=r"((r)[0]), "=r"((r)[1]), "=r"((r)[2]), "=r"((r)[3]) \
                 : "r"(addr))

#define MMA_BF16(acc, a, b0, b1) \
    asm volatile("mma.sync.aligned.m16n8k16.row.col.f32.bf16.bf16.f32 " \
                 "{%0,%1,%2,%3}, {%4,%5,%6,%7}, {%8,%9}, {%0,%1,%2,%3};" \
                 : "+f"((acc)[0]), "+f"((acc)[1]), "+f"((acc)[2]), "+f"((acc)[3]) \
                 : "r"((a)[0]), "r"((a)[1]), "r"((a)[2]), "r"((a)[3]), \
                   "r"(b0), "r"(b1))

__device__ __forceinline__ uint32_t pack_bf162(float a, float b) {
    __nv_bfloat162 p;
    p.x = __float2bfloat16_rn(a);
    p.y = __float2bfloat16_rn(b);
    return *reinterpret_cast<uint32_t*>(&p);
}

// accumulate 8 fp16 values (as uint4) into 8 fp32 accumulators
__device__ __forceinline__ void add8h(float* acc, uint4 v) {
    const __half2* h = reinterpret_cast<const __half2*>(&v);
    #pragma unroll
    for (int i = 0; i < 4; i++) {
        float2 f = __half22float2(h[i]);
        acc[2 * i]     += f.x;
        acc[2 * i + 1] += f.y;
    }
}

// ---------------- fill (2 edges/thread) + packed split-W setup -------------
__global__ void fill_setup_kernel(const int* __restrict__ src,
                                  const int* __restrict__ dst,
                                  const float* __restrict__ W1,
                                  const float* __restrict__ W2,
                                  const float* __restrict__ W3) {
    int t = blockIdx.x * blockDim.x + threadIdx.x;
    if (t < 20480) {
        const float* W;
        int rel;
        if (t < 8192)       { W = W1; rel = t; }
        else if (t < 16384) { W = W2; rel = t - 8192; }
        else                { W = W3; rel = t - 16384; }
        int n  = rel >> 6;
        int kp = rel & 63;
        float v0 = W[n * 128 + kp * 2 + 0];
        float v1 = W[n * 128 + kp * 2 + 1];
        __nv_bfloat16 h0 = __float2bfloat16_rn(v0);
        __nv_bfloat16 h1 = __float2bfloat16_rn(v1);
        __nv_bfloat162 hi; hi.x = h0; hi.y = h1;
        uint2 o;
        o.x = *reinterpret_cast<uint32_t*>(&hi);
        o.y = pack_bf162(v0 - __bfloat162float(h0), v1 - __bfloat162float(h1));
        g_wp[t] = o;
    }
    int e = t * 2;
    if (e < N_EDGES) {
        int2 s2 = *reinterpret_cast<const int2*>(src + e);
        int2 d2 = *reinterpret_cast<const int2*>(dst + e);
        int p = atomicAdd(&g_count[d2.x], 1);
        if (p < CAP) g_slot[d2.x * CAP + p] = s2.x;
        p = atomicAdd(&g_count[d2.y], 1);
        if (p < CAP) g_slot[d2.y * CAP + p] = s2.y;
    }
}

// ---------------- layer-1 GEMM: Zh = x @ W1^T (fp32 in, fp16 out) ----------
// R7-proven: 128 threads, A staged+split to bf16 hi/lo in smem.
template <int N>
__global__ void __launch_bounds__(128, 2) mma_gemm(
    const float* __restrict__ A, const uint2* __restrict__ Wp,
    __half* __restrict__ Zh) {
    constexpr int NT = N / 8;
    extern __shared__ __nv_bfloat16 smem[];
    __nv_bfloat16* Ash = smem;
    __nv_bfloat16* Asl = smem + 128 * LDA;

    const int tid  = threadIdx.x;
    const int wid  = tid >> 5;
    const int lane = tid & 31;
    const int m0   = blockIdx.x * 128;

    for (int t = tid; t < 4096; t += 128) {
        int r = t >> 5;
        int c = (t & 31) << 2;
        int m = m0 + r;
        float4 v = make_float4(0.f, 0.f, 0.f, 0.f);
        if (m < N_NODES)
            v = *reinterpret_cast<const float4*>(A + (size_t)m * 128 + c);
        __nv_bfloat16 h0 = __float2bfloat16_rn(v.x);
        __nv_bfloat16 h1 = __float2bfloat16_rn(v.y);
        __nv_bfloat16 h2 = __float2bfloat16_rn(v.z);
        __nv_bfloat16 h3 = __float2bfloat16_rn(v.w);
        __nv_bfloat162 hp0; hp0.x = h0; hp0.y = h1;
        __nv_bfloat162 hp1; hp1.x = h2; hp1.y = h3;
        uint2 hv, lv;
        hv.x = *reinterpret_cast<uint32_t*>(&hp0);
        hv.y = *reinterpret_cast<uint32_t*>(&hp1);
        lv.x = pack_bf162(v.x - __bfloat162float(h0), v.y - __bfloat162float(h1));
        lv.y = pack_bf162(v.z - __bfloat162float(h2), v.w - __bfloat162float(h3));
        *reinterpret_cast<uint2*>(Ash + r * LDA + c) = hv;
        *reinterpret_cast<uint2*>(Asl + r * LDA + c) = lv;
    }
    __syncthreads();

    float acc[2][NT][4];
    #pragma unroll
    for (int mt = 0; mt < 2; mt++)
        #pragma unroll
        for (int nt = 0; nt < NT; nt++)
            #pragma unroll
            for (int i = 0; i < 4; i++) acc[mt][nt][i] = 0.0f;

    const int wrow = wid * 32;
    const int lrow = lane & 15;
    const int kgrp = (lane >> 4) * 8;
    const int wn   = lane >> 2;
    const int wkp  = lane & 3;

    #pragma unroll
    for (int ks = 0; ks < 8; ks++) {
        const int k0 = ks * 16;
        uint32_t ah[2][4], al[2][4];
        #pragma unroll
        for (int mt = 0; mt < 2; mt++) {
            uint32_t ad = smem_u32(Ash + (wrow + mt * 16 + lrow) * LDA + k0 + kgrp);
            LDMATRIX_X4(ah[mt], ad);
            uint32_t bd = smem_u32(Asl + (wrow + mt * 16 + lrow) * LDA + k0 + kgrp);
            LDMATRIX_X4(al[mt], bd);
        }
        #pragma unroll
        for (int nt = 0; nt < NT; nt++) {
            const uint2* wp = Wp + (size_t)(nt * 8 + wn) * 64 + (k0 >> 1) + wkp;
            uint2 p0 = wp[0];
            uint2 p1 = wp[4];
            #pragma unroll
            for (int mt = 0; mt < 2; mt++) {
                MMA_BF16(acc[mt][nt], ah[mt], p0.x, p1.x);
                MMA_BF16(acc[mt][nt], ah[mt], p0.y, p1.y);
                MMA_BF16(acc[mt][nt], al[mt], p0.x, p1.x);
            }
        }
    }

    #pragma unroll
    for (int mt = 0; mt < 2; mt++) {
        int r0 = m0 + wrow + mt * 16 + (lane >> 2);
        #pragma unroll
        for (int nt = 0; nt < NT; nt++) {
            int col = nt * 8 + (lane & 3) * 2;
            if (r0 < N_NODES) {
                __half2 hv = __floats2half2_rn(acc[mt][nt][0], acc[mt][nt][1]);
                *reinterpret_cast<__half2*>(Zh + (size_t)r0 * N + col) = hv;
            }
            if (r0 + 8 < N_NODES) {
                __half2 hv = __floats2half2_rn(acc[mt][nt][2], acc[mt][nt][3]);
                *reinterpret_cast<__half2*>(Zh + (size_t)(r0 + 8) * N + col) = hv;
            }
        }
    }
}

// ---------------- fused agg128 + GEMM: Zout = relu_agg(Zin) @ W^T ----------
// 512 threads. Phase 1: 16 warps x 8 nodes, R7 gather loop, write split-bf16
// h directly into the GEMM smem tiles. Phase 2: 16 warps = 8 m16-tiles x 2
// column halves of the proven mma mainloop.
template <int NOUT>
__global__ void __launch_bounds__(512, 2) fused_agg_gemm(
    const __half* __restrict__ Zin, const uint2* __restrict__ Wp,
    __half* __restrict__ Zout) {
    constexpr int NTW = NOUT / 16;   // n-tiles per warp (each half of NOUT/8)
    extern __shared__ __nv_bfloat16 smem[];
    __nv_bfloat16* Ash = smem;
    __nv_bfloat16* Asl = smem + 128 * LDA;

    const int tid  = threadIdx.x;
    const int wid  = tid >> 5;
    const int lane = tid & 31;
    const int m0   = blockIdx.x * 128;
    const int g    = lane >> 4;
    const int c    = lane & 15;

    // ---- phase 1: aggregate 8 nodes per warp ----
    for (int i = 0; i < 8; i++) {
        int r = wid * 8 + i;
        int node = m0 + r;
        float acc[8];
        #pragma unroll
        for (int k = 0; k < 8; k++) acc[k] = 0.f;
        int cnt = 0;
        if (node < N_NODES) {
            if (g == 0) {
                uint4 v = *reinterpret_cast<const uint4*>(
                    Zin + (size_t)node * 128 + c * 8);
                add8h(acc, v);
            }
            cnt = g_count[node];
            int deg = cnt < CAP ? cnt : CAP;
            const int* sl = &g_slot[node * CAP];
            int j = g;
            int idx = (j < deg) ? sl[j] : 0;
            while (j < deg) {
                int jn = j + 2;
                int idxn = (jn < deg) ? sl[jn] : 0;   // prefetch next index
                uint4 v = *reinterpret_cast<const uint4*>(
                    Zin + (size_t)idx * 128 + c * 8);
                add8h(acc, v);
                j = jn; idx = idxn;
            }
        }
        __syncwarp();
        #pragma unroll
        for (int k = 0; k < 8; k++)
            acc[k] += __shfl_down_sync(0xffffffffu, acc[k], 16);

        if (g == 0) {
            float sc = 1.0f / ((float)cnt + 1.0f);
            float o[8];
            #pragma unroll
            for (int k = 0; k < 8; k++) o[k] = fmaxf(acc[k] * sc, 0.f);
            __nv_bfloat16 hb[8];
            #pragma unroll
            for (int k = 0; k < 8; k++) hb[k] = __float2bfloat16_rn(o[k]);
            uint4 hv, lv;
            {
                __nv_bfloat162 p01; p01.x = hb[0]; p01.y = hb[1];
                __nv_bfloat162 p23; p23.x = hb[2]; p23.y = hb[3];
                __nv_bfloat162 p45; p45.x = hb[4]; p45.y = hb[5];
                __nv_bfloat162 p67; p67.x = hb[6]; p67.y = hb[7];
                hv.x = *reinterpret_cast<uint32_t*>(&p01);
                hv.y = *reinterpret_cast<uint32_t*>(&p23);
                hv.z = *reinterpret_cast<uint32_t*>(&p45);
                hv.w = *reinterpret_cast<uint32_t*>(&p67);
            }
            lv.x = pack_bf162(o[0] - __bfloat162float(hb[0]),
                              o[1] - __bfloat162float(hb[1]));
            lv.y = pack_bf162(o[2] - __bfloat162float(hb[2]),
                              o[3] - __bfloat162float(hb[3]));
            lv.z = pack_bf162(o[4] - __bfloat162float(hb[4]),
                              o[5] - __bfloat162float(hb[5]));
            lv.w = pack_bf162(o[6] - __bfloat162float(hb[6]),
                              o[7] - __bfloat162float(hb[7]));
            *reinterpret_cast<uint4*>(Ash + r * LDA + c * 8) = hv;
            *reinterpret_cast<uint4*>(Asl + r * LDA + c * 8) = lv;
        }
    }
    __syncthreads();

    // ---- phase 2: GEMM. warp = (m16 tile wtile, column half chalf) ----
    const int wtile = wid >> 1;      // 0..7
    const int chalf = wid & 1;       // 0..1
    float acc[NTW][4];
    #pragma unroll
    for (int nt = 0; nt < NTW; nt++)
        #pragma unroll
        for (int i = 0; i < 4; i++) acc[nt][i] = 0.0f;

    const int lrow = lane & 15;
    const int kgrp = (lane >> 4) * 8;
    const int wn   = lane >> 2;
    const int wkp  = lane & 3;

    #pragma unroll
    for (int ks = 0; ks < 8; ks++) {
        const int k0 = ks * 16;
        uint32_t ah[4], al[4];
        uint32_t ad = smem_u32(Ash + (wtile * 16 + lrow) * LDA + k0 + kgrp);
        LDMATRIX_X4(ah, ad);
        uint32_t bd = smem_u32(Asl + (wtile * 16 + lrow) * LDA + k0 + kgrp);
        LDMATRIX_X4(al, bd);
        #pragma unroll
        for (int nt = 0; nt < NTW; nt++) {
            int ntg = chalf * NTW + nt;
            const uint2* wp = Wp + (size_t)(ntg * 8 + wn) * 64 + (k0 >> 1) + wkp;
            uint2 p0 = wp[0];
            uint2 p1 = wp[4];
            MMA_BF16(acc[nt], ah, p0.x, p1.x);
            MMA_BF16(acc[nt], ah, p0.y, p1.y);
            MMA_BF16(acc[nt], al, p0.x, p1.x);
        }
    }

    int r0 = m0 + wtile * 16 + (lane >> 2);
    #pragma unroll
    for (int nt = 0; nt < NTW; nt++) {
        int col = (chalf * NTW + nt) * 8 + (lane & 3) * 2;
        if (r0 < N_NODES) {
            __half2 hv = __floats2half2_rn(acc[nt][0], acc[nt][1]);
            *reinterpret_cast<__half2*>(Zout + (size_t)r0 * NOUT + col) = hv;
        }
        if (r0 + 8 < N_NODES) {
            __half2 hv = __floats2half2_rn(acc[nt][2], acc[nt][3]);
            *reinterpret_cast<__half2*>(Zout + (size_t)(r0 + 8) * NOUT + col) = hv;
        }
    }
}

// ---------------- final agg: 64-dim fp16 z -> fp32 out ---------------------
// Warp = 4 groups of 8 lanes. Re-zeroes g_count for graph-replay determinism.
__global__ void agg64_kernel(const __half* __restrict__ Z,
                             float* __restrict__ out) {
    int node = (blockIdx.x * blockDim.x + threadIdx.x) >> 5;
    if (node >= N_NODES) return;
    int lane = threadIdx.x & 31;
    int g = lane >> 3;
    int c = lane & 7;

    float acc[8];
    #pragma unroll
    for (int i = 0; i < 8; i++) acc[i] = 0.f;

    if (g == 0) {
        uint4 v = *reinterpret_cast<const uint4*>(Z + (size_t)node * 64 + c * 8);
        add8h(acc, v);
    }

    int cnt = g_count[node];
    int deg = cnt < CAP ? cnt : CAP;
    const int* sl = &g_slot[node * CAP];

    int j = g;
    int idx = (j < deg) ? sl[j] : 0;
    while (j < deg) {
        int jn = j + 4;
        int idxn = (jn < deg) ? sl[jn] : 0;
        uint4 v = *reinterpret_cast<const uint4*>(Z + (size_t)idx * 64 + c * 8);
        add8h(acc, v);
        j = jn; idx = idxn;
    }

    __syncwarp();
    #pragma unroll
    for (int i = 0; i < 8; i++)
        acc[i] += __shfl_down_sync(0xffffffffu, acc[i], 16);
    #pragma unroll
    for (int i = 0; i < 8; i++)
        acc[i] += __shfl_down_sync(0xffffffffu, acc[i], 8);

    if (lane < 8) {
        float sc = 1.0f / ((float)cnt + 1.0f);
        float4 o0 = make_float4(fmaxf(acc[0] * sc, 0.f), fmaxf(acc[1] * sc, 0.f),
                                fmaxf(acc[2] * sc, 0.f), fmaxf(acc[3] * sc, 0.f));
        float4 o1 = make_float4(fmaxf(acc[4] * sc, 0.f), fmaxf(acc[5] * sc, 0.f),
                                fmaxf(acc[6] * sc, 0.f), fmaxf(acc[7] * sc, 0.f));
        float4* dst = reinterpret_cast<float4*>(out + (size_t)node * 64 + c * 8);
        dst[0] = o0;
        dst[1] = o1;
    }
    if (lane == 0) g_count[node] = 0;   // reset for next launch / replay
}

// ---------------- launch ----------------
extern "C" void kernel_launch(void* const* d_in, const int* in_sizes, int n_in,
                              void* d_out, int out_size) {
    const float* x   = (const float*)d_in[0];
    const int*   ei  = (const int*)d_in[1];
    const float* W1  = (const float*)d_in[2];
    const float* W2  = (const float*)d_in[3];
    const float* W3  = (const float*)d_in[4];
    float*       out = (float*)d_out;

    const int* src = ei;
    const int* dst = ei + N_EDGES;

    __half* za = nullptr;
    __half* zb = nullptr;
    uint2*  wp = nullptr;
    cudaGetSymbolAddress((void**)&za, g_za);
    cudaGetSymbolAddress((void**)&zb, g_zb);
    cudaGetSymbolAddress((void**)&wp, g_wp);

    constexpr int SMEM_A = 2 * 128 * LDA * 2;   // 69632 bytes
    cudaFuncSetAttribute(mma_gemm<128>,
                         cudaFuncAttributeMaxDynamicSharedMemorySize, SMEM_A);
    cudaFuncSetAttribute(fused_agg_gemm<128>,
                         cudaFuncAttributeMaxDynamicSharedMemorySize, SMEM_A);
    cudaFuncSetAttribute(fused_agg_gemm<64>,
                         cudaFuncAttributeMaxDynamicSharedMemorySize, SMEM_A);

    const int TPB = 256;
    const int blocks128 = (N_NODES + 127) / 128;              // 391
    const int agg_blocks = (N_NODES * 32 + TPB - 1) / TPB;    // 6250
    const int fill_blocks = (N_EDGES / 2 + TPB - 1) / TPB;    // 1563

    fill_setup_kernel<<<fill_blocks, TPB>>>(src, dst, W1, W2, W3);

    // layer 1: z_a = x @ W1^T
    mma_gemm<128><<<blocks128, 128, SMEM_A>>>(x, wp, za);
    // layer 2 fused: h1 = relu(agg(z_a)); z_b = h1 @ W2^T
    fused_agg_gemm<128><<<blocks128, 512, SMEM_A>>>(za, wp + 8192, zb);
    // layer 3 fused: h2 = relu(agg(z_b)); z_a = h2 @ W3^T (64 cols)
    fused_agg_gemm<64><<<blocks128, 512, SMEM_A>>>(zb, wp + 16384, za);
    // final: out = relu(agg(z_a))
    agg64_kernel<<<agg_blocks, TPB>>>(za, out);
}

// round 10
// speedup vs baseline: 1.4732x; 1.3086x over previous
#include <cuda_runtime.h>
#include <cuda_bf16.h>
#include <cuda_fp16.h>
#include <cstdint>

#define N_NODES 50000
#define N_EDGES 800000
#define CAP 64
#define LDA 136

// ---------------- scratch (device globals; no allocation allowed) ----------
__device__ int    g_count[N_NODES];           // zero-init; re-zeroed by agg64
__device__ int    g_slot[N_NODES * CAP];
__device__ __half g_zh[N_NODES * 128];        // GEMM output, fp16
__device__ float  g_h[N_NODES * 128];         // agg output, fp32
// packed split weights: per (n, k-pair): {hi[k],hi[k+1]} , {lo[k],lo[k+1]}
// W1: 8192 uint2 | W2: 8192 | W3: 4096
__device__ uint2  g_wp[20480];

// ---------------- small helpers ----------------
__device__ __forceinline__ uint32_t smem_u32(const void* p) {
    uint32_t a;
    asm("{ .reg .u64 t; cvta.to.shared.u64 t, %1; cvt.u32.u64 %0, t; }"
        : "=r"(a) : "l"(p));
    return a;
}

#define LDMATRIX_X4(r, addr) \
    asm volatile("ldmatrix.sync.aligned.m8n8.x4.shared.b16 {%0,%1,%2,%3}, [%4];" \
                 : "=r"((r)[0]), "=r"((r)[1]), "=r"((r)[2]), "=r"((r)[3]) \
                 : "r"(addr))

#define MMA_BF16(acc, a, b0, b1) \
    asm volatile("mma.sync.aligned.m16n8k16.row.col.f32.bf16.bf16.f32 " \
                 "{%0,%1,%2,%3}, {%4,%5,%6,%7}, {%8,%9}, {%0,%1,%2,%3};" \
                 : "+f"((acc)[0]), "+f"((acc)[1]), "+f"((acc)[2]), "+f"((acc)[3]) \
                 : "r"((a)[0]), "r"((a)[1]), "r"((a)[2]), "r"((a)[3]), \
                   "r"(b0), "r"(b1))

__device__ __forceinline__ uint32_t pack_bf162(float a, float b) {
    __nv_bfloat162 p;
    p.x = __float2bfloat16_rn(a);
    p.y = __float2bfloat16_rn(b);
    return *reinterpret_cast<uint32_t*>(&p);
}

// accumulate 8 fp16 values (as uint4) into 8 fp32 accumulators (exact)
__device__ __forceinline__ void add8h(float* acc, uint4 v) {
    const __half2* h = reinterpret_cast<const __half2*>(&v);
    #pragma unroll
    for (int i = 0; i < 4; i++) {
        float2 f = __half22float2(h[i]);
        acc[2 * i]     += f.x;
        acc[2 * i + 1] += f.y;
    }
}

// sum two fp16 rows pairwise in fp16 (1 rounding), flush to fp32
__device__ __forceinline__ void pair_flush(float* acc, uint4 a, uint4 b) {
    const __half2* pa = reinterpret_cast<const __half2*>(&a);
    const __half2* pb = reinterpret_cast<const __half2*>(&b);
    #pragma unroll
    for (int i = 0; i < 4; i++) {
        __half2 s = __hadd2(pa[i], pb[i]);
        float2 f = __half22float2(s);
        acc[2 * i]     += f.x;
        acc[2 * i + 1] += f.y;
    }
}

// ---------------- fill (2 edges/thread) + packed split-W setup -------------
__global__ void fill_setup_kernel(const int* __restrict__ src,
                                  const int* __restrict__ dst,
                                  const float* __restrict__ W1,
                                  const float* __restrict__ W2,
                                  const float* __restrict__ W3) {
    int t = blockIdx.x * blockDim.x + threadIdx.x;
    if (t < 20480) {
        const float* W;
        int rel;
        if (t < 8192)       { W = W1; rel = t; }
        else if (t < 16384) { W = W2; rel = t - 8192; }
        else                { W = W3; rel = t - 16384; }
        int n  = rel >> 6;
        int kp = rel & 63;
        float v0 = W[n * 128 + kp * 2 + 0];
        float v1 = W[n * 128 + kp * 2 + 1];
        __nv_bfloat16 h0 = __float2bfloat16_rn(v0);
        __nv_bfloat16 h1 = __float2bfloat16_rn(v1);
        __nv_bfloat162 hi; hi.x = h0; hi.y = h1;
        uint2 o;
        o.x = *reinterpret_cast<uint32_t*>(&hi);
        o.y = pack_bf162(v0 - __bfloat162float(h0), v1 - __bfloat162float(h1));
        g_wp[t] = o;
    }
    int e = t * 2;
    if (e < N_EDGES) {
        int2 s2 = *reinterpret_cast<const int2*>(src + e);
        int2 d2 = *reinterpret_cast<const int2*>(dst + e);
        int p = atomicAdd(&g_count[d2.x], 1);
        if (p < CAP) g_slot[d2.x * CAP + p] = s2.x;
        p = atomicAdd(&g_count[d2.y], 1);
        if (p < CAP) g_slot[d2.y * CAP + p] = s2.y;
    }
}

// ---------------- mma.sync split-bf16 GEMM: Zh[128-tile][N] = A @ W^T ------
template <int N>
__global__ void __launch_bounds__(128, 2) mma_gemm(
    const float* __restrict__ A, const uint2* __restrict__ Wp,
    __half* __restrict__ Zh) {
    constexpr int NT = N / 8;
    extern __shared__ __nv_bfloat16 smem[];
    __nv_bfloat16* Ash = smem;
    __nv_bfloat16* Asl = smem + 128 * LDA;

    const int tid  = threadIdx.x;
    const int wid  = tid >> 5;
    const int lane = tid & 31;
    const int m0   = blockIdx.x * 128;

    for (int t = tid; t < 4096; t += 128) {
        int r = t >> 5;
        int c = (t & 31) << 2;
        int m = m0 + r;
        float4 v = make_float4(0.f, 0.f, 0.f, 0.f);
        if (m < N_NODES)
            v = *reinterpret_cast<const float4*>(A + (size_t)m * 128 + c);
        __nv_bfloat16 h0 = __float2bfloat16_rn(v.x);
        __nv_bfloat16 h1 = __float2bfloat16_rn(v.y);
        __nv_bfloat16 h2 = __float2bfloat16_rn(v.z);
        __nv_bfloat16 h3 = __float2bfloat16_rn(v.w);
        __nv_bfloat162 hp0; hp0.x = h0; hp0.y = h1;
        __nv_bfloat162 hp1; hp1.x = h2; hp1.y = h3;
        uint2 hv, lv;
        hv.x = *reinterpret_cast<uint32_t*>(&hp0);
        hv.y = *reinterpret_cast<uint32_t*>(&hp1);
        lv.x = pack_bf162(v.x - __bfloat162float(h0), v.y - __bfloat162float(h1));
        lv.y = pack_bf162(v.z - __bfloat162float(h2), v.w - __bfloat162float(h3));
        *reinterpret_cast<uint2*>(Ash + r * LDA + c) = hv;
        *reinterpret_cast<uint2*>(Asl + r * LDA + c) = lv;
    }
    __syncthreads();

    float acc[2][NT][4];
    #pragma unroll
    for (int mt = 0; mt < 2; mt++)
        #pragma unroll
        for (int nt = 0; nt < NT; nt++)
            #pragma unroll
            for (int i = 0; i < 4; i++) acc[mt][nt][i] = 0.0f;

    const int wrow = wid * 32;
    const int lrow = lane & 15;
    const int kgrp = (lane >> 4) * 8;
    const int wn   = lane >> 2;
    const int wkp  = lane & 3;

    #pragma unroll
    for (int ks = 0; ks < 8; ks++) {
        const int k0 = ks * 16;
        uint32_t ah[2][4], al[2][4];
        #pragma unroll
        for (int mt = 0; mt < 2; mt++) {
            uint32_t ad = smem_u32(Ash + (wrow + mt * 16 + lrow) * LDA + k0 + kgrp);
            LDMATRIX_X4(ah[mt], ad);
            uint32_t bd = smem_u32(Asl + (wrow + mt * 16 + lrow) * LDA + k0 + kgrp);
            LDMATRIX_X4(al[mt], bd);
        }
        #pragma unroll
        for (int nt = 0; nt < NT; nt++) {
            const uint2* wp = Wp + (size_t)(nt * 8 + wn) * 64 + (k0 >> 1) + wkp;
            uint2 p0 = wp[0];
            uint2 p1 = wp[4];
            #pragma unroll
            for (int mt = 0; mt < 2; mt++) {
                MMA_BF16(acc[mt][nt], ah[mt], p0.x, p1.x);
                MMA_BF16(acc[mt][nt], ah[mt], p0.y, p1.y);
                MMA_BF16(acc[mt][nt], al[mt], p0.x, p1.x);
            }
        }
    }

    #pragma unroll
    for (int mt = 0; mt < 2; mt++) {
        int r0 = m0 + wrow + mt * 16 + (lane >> 2);
        #pragma unroll
        for (int nt = 0; nt < NT; nt++) {
            int col = nt * 8 + (lane & 3) * 2;
            if (r0 < N_NODES) {
                __half2 hv = __floats2half2_rn(acc[mt][nt][0], acc[mt][nt][1]);
                *reinterpret_cast<__half2*>(Zh + (size_t)r0 * N + col) = hv;
            }
            if (r0 + 8 < N_NODES) {
                __half2 hv = __floats2half2_rn(acc[mt][nt][2], acc[mt][nt][3]);
                *reinterpret_cast<__half2*>(Zh + (size_t)(r0 + 8) * N + col) = hv;
            }
        }
    }
}

// ---------------- gather + self + inv-scale + relu (fp16 z) ----------------
// R7 pipeline shape (rolling index prefetch) with two rows in flight and a
// pairwise fp16 add (1 rounding) before the fp32 flush.
__global__ void agg128_kernel(const __half* __restrict__ Z,
                              float* __restrict__ H) {
    int node = (blockIdx.x * blockDim.x + threadIdx.x) >> 5;
    if (node >= N_NODES) return;
    int lane = threadIdx.x & 31;
    int g = lane >> 4;
    int c = lane & 15;

    float acc[8];
    #pragma unroll
    for (int i = 0; i < 8; i++) acc[i] = 0.f;

    if (g == 0) {
        uint4 v = *reinterpret_cast<const uint4*>(Z + (size_t)node * 128 + c * 8);
        add8h(acc, v);
    }

    int cnt = g_count[node];
    int deg = cnt < CAP ? cnt : CAP;
    const int* sl = &g_slot[node * CAP];

    // group g owns neighbors g, g+2, g+4, ...
    int j = g;
    int i0 = (j < deg)     ? sl[j]     : 0;
    int i1 = (j + 2 < deg) ? sl[j + 2] : 0;
    while (j + 2 < deg) {
        int jn = j + 4;
        int n0 = (jn < deg)     ? sl[jn]     : 0;   // prefetch next pair
        int n1 = (jn + 2 < deg) ? sl[jn + 2] : 0;
        uint4 v0 = *reinterpret_cast<const uint4*>(Z + (size_t)i0 * 128 + c * 8);
        uint4 v1 = *reinterpret_cast<const uint4*>(Z + (size_t)i1 * 128 + c * 8);
        pair_flush(acc, v0, v1);
        j = jn; i0 = n0; i1 = n1;
    }
    if (j < deg) {
        uint4 v = *reinterpret_cast<const uint4*>(Z + (size_t)i0 * 128 + c * 8);
        add8h(acc, v);
    }

    __syncwarp();
    #pragma unroll
    for (int i = 0; i < 8; i++)
        acc[i] += __shfl_down_sync(0xffffffffu, acc[i], 16);

    if (g == 0) {
        float sc = 1.0f / ((float)cnt + 1.0f);
        float4 o0 = make_float4(fmaxf(acc[0] * sc, 0.f), fmaxf(acc[1] * sc, 0.f),
                                fmaxf(acc[2] * sc, 0.f), fmaxf(acc[3] * sc, 0.f));
        float4 o1 = make_float4(fmaxf(acc[4] * sc, 0.f), fmaxf(acc[5] * sc, 0.f),
                                fmaxf(acc[6] * sc, 0.f), fmaxf(acc[7] * sc, 0.f));
        float4* dst = reinterpret_cast<float4*>(H + (size_t)node * 128 + c * 8);
        dst[0] = o0;
        dst[1] = o1;
    }
}

// Final layer: 64-dim fp16 z, fp32 output. Warp = 4 groups of 8 lanes.
// Also re-zeroes g_count for graph-replay determinism.
__global__ void agg64_kernel(const __half* __restrict__ Z,
                             float* __restrict__ out) {
    int node = (blockIdx.x * blockDim.x + threadIdx.x) >> 5;
    if (node >= N_NODES) return;
    int lane = threadIdx.x & 31;
    int g = lane >> 3;
    int c = lane & 7;

    float acc[8];
    #pragma unroll
    for (int i = 0; i < 8; i++) acc[i] = 0.f;

    if (g == 0) {
        uint4 v = *reinterpret_cast<const uint4*>(Z + (size_t)node * 64 + c * 8);
        add8h(acc, v);
    }

    int cnt = g_count[node];
    int deg = cnt < CAP ? cnt : CAP;
    const int* sl = &g_slot[node * CAP];

    int j = g;
    int idx = (j < deg) ? sl[j] : 0;
    while (j < deg) {
        int jn = j + 4;
        int idxn = (jn < deg) ? sl[jn] : 0;
        uint4 v = *reinterpret_cast<const uint4*>(Z + (size_t)idx * 64 + c * 8);
        add8h(acc, v);
        j = jn; idx = idxn;
    }

    __syncwarp();
    #pragma unroll
    for (int i = 0; i < 8; i++)
        acc[i] += __shfl_down_sync(0xffffffffu, acc[i], 16);
    #pragma unroll
    for (int i = 0; i < 8; i++)
        acc[i] += __shfl_down_sync(0xffffffffu, acc[i], 8);

    if (lane < 8) {
        float sc = 1.0f / ((float)cnt + 1.0f);
        float4 o0 = make_float4(fmaxf(acc[0] * sc, 0.f), fmaxf(acc[1] * sc, 0.f),
                                fmaxf(acc[2] * sc, 0.f), fmaxf(acc[3] * sc, 0.f));
        float4 o1 = make_float4(fmaxf(acc[4] * sc, 0.f), fmaxf(acc[5] * sc, 0.f),
                                fmaxf(acc[6] * sc, 0.f), fmaxf(acc[7] * sc, 0.f));
        float4* dst = reinterpret_cast<float4*>(out + (size_t)node * 64 + c * 8);
        dst[0] = o0;
        dst[1] = o1;
    }
    if (lane == 0) g_count[node] = 0;   // reset for next launch / replay
}

// ---------------- launch ----------------
extern "C" void kernel_launch(void* const* d_in, const int* in_sizes, int n_in,
                              void* d_out, int out_size) {
    const float* x   = (const float*)d_in[0];
    const int*   ei  = (const int*)d_in[1];
    const float* W1  = (const float*)d_in[2];
    const float* W2  = (const float*)d_in[3];
    const float* W3  = (const float*)d_in[4];
    float*       out = (float*)d_out;

    const int* src = ei;
    const int* dst = ei + N_EDGES;

    __half* zh = nullptr;
    float*  h  = nullptr;
    uint2*  wp = nullptr;
    cudaGetSymbolAddress((void**)&zh, g_zh);
    cudaGetSymbolAddress((void**)&h,  g_h);
    cudaGetSymbolAddress((void**)&wp, g_wp);

    constexpr int SMEM_A = 2 * 128 * LDA * 2;   // 69632 bytes
    cudaFuncSetAttribute(mma_gemm<128>,
                         cudaFuncAttributeMaxDynamicSharedMemorySize, SMEM_A);
    cudaFuncSetAttribute(mma_gemm<64>,
                         cudaFuncAttributeMaxDynamicSharedMemorySize, SMEM_A);

    const int TPB = 256;
    const int gemm_blocks = (N_NODES + 127) / 128;             // 391
    const int agg_blocks  = (N_NODES * 32 + TPB - 1) / TPB;    // 6250
    const int fill_blocks = (N_EDGES / 2 + TPB - 1) / TPB;     // 1563

    fill_setup_kernel<<<fill_blocks, TPB>>>(src, dst, W1, W2, W3);

    // layer 1
    mma_gemm<128><<<gemm_blocks, 128, SMEM_A>>>(x, wp, zh);
    agg128_kernel<<<agg_blocks, TPB>>>(zh, h);
    // layer 2
    mma_gemm<128><<<gemm_blocks, 128, SMEM_A>>>(h, wp + 8192, zh);
    agg128_kernel<<<agg_blocks, TPB>>>(zh, h);
    // layer 3 (N=64), final relu + write out
    mma_gemm<64><<<gemm_blocks, 128, SMEM_A>>>(h, wp + 16384, zh);
    agg64_kernel<<<agg_blocks, TPB>>>(zh, out);
}